// round 8
// baseline (speedup 1.0000x reference)
#include <cuda_runtime.h>
#include <cuda_bf16.h>
#include <cstdint>
#include <math.h>

#define NB     16384
#define GB     4              // batches per block (16384 = 4096 * 4, exact)
#define ROWS   56             // 4 * 14 rows used (pad to 64)
#define DIM    256

// Pre-converted, pre-swizzled L operand: 4 k-chunks of [256 e-rows x 64 k] bf16
__device__ __nv_bfloat16 g_Lh[4 * 256 * 64];
__device__ __nv_bfloat16 g_Ll[4 * 256 * 64];
__device__ float g_signorm[4 * DIM];

// ---------------- helpers ----------------
__device__ __forceinline__ uint32_t smem_u32(const void* p) {
    uint32_t a;
    asm("{ .reg .u64 t; cvta.to.shared.u64 t, %1; cvt.u32.u64 %0, t; }" : "=r"(a) : "l"(p));
    return a;
}
#define SWZ128(off) ((off) ^ (((off) >> 3) & 0x70))

#define LDSM4(r, addr)                                                          \
    asm volatile("ldmatrix.sync.aligned.m8n8.x4.shared.b16 {%0,%1,%2,%3}, [%4];"\
        : "=r"((r)[0]), "=r"((r)[1]), "=r"((r)[2]), "=r"((r)[3]) : "r"(addr))

#define MMA_BF16(d, a, b)                                                       \
    asm volatile("mma.sync.aligned.m16n8k16.row.col.f32.bf16.bf16.f32 "         \
        "{%0,%1,%2,%3}, {%4,%5,%6,%7}, {%8,%9}, {%0,%1,%2,%3};"                 \
        : "+f"((d)[0]), "+f"((d)[1]), "+f"((d)[2]), "+f"((d)[3])                \
        : "r"((a)[0]), "r"((a)[1]), "r"((a)[2]), "r"((a)[3]),                   \
          "r"((b)[0]), "r"((b)[1]))

// ---------------- prep kernels ----------------
__global__ void k_signorm(const float* __restrict__ sigs)
{
    int w = threadIdx.x >> 5, lane = threadIdx.x & 31;
    if (w < 4) {
        const float* s = sigs + w * DIM;
        float acc = 0.f;
        for (int d = lane; d < DIM; d += 32) { float v = s[d]; acc = fmaf(v, v, acc); }
        #pragma unroll
        for (int o = 16; o; o >>= 1) acc += __shfl_xor_sync(0xffffffffu, acc, o);
        float inv = 1.0f / fmaxf(sqrtf(acc), 1e-12f);
        for (int d = lane; d < DIM; d += 32) g_signorm[w * DIM + d] = s[d] * inv;
    }
}

__global__ void k_prepL(const float* __restrict__ L)
{
    int r = blockIdx.x;            // e-row 0..255
    int k = threadIdx.x;           // k   0..255
    float x = L[r * 256 + k];
    __nv_bfloat16 h = __float2bfloat16(x);
    __nv_bfloat16 l = __float2bfloat16(x - __bfloat162float(h));
    int c  = k >> 6;
    int kc = k & 63;
    uint32_t off = SWZ128((uint32_t)(r * 128 + kc * 2));
    g_Lh[c * 16384 + (off >> 1)] = h;
    g_Ll[c * 16384 + (off >> 1)] = l;
}

// ---------------- fused kernel ----------------
// smem layout (bytes):
#define OFF_Y     0                  // 56 rows x 256 f32    = 57344
#define OFF_AH    57344              // 64 x 64 bf16         = 8192
#define OFF_AL    65536              // 8192
#define OFF_BH    73728              // 128 e-rows x 64 bf16 = 16384
#define OFF_BL    90112              // 16384
#define OFF_DANG  106496             // 4 x 256 f32          = 4096
#define OFF_ROWST 110592             // 56 rows x 6 f32      = 1344
#define OFF_STATS 111936             // 4*62 f32             = 992
#define SMEM_TOT  112928

__global__ void __launch_bounds__(256, 2)
k_fused(const float* __restrict__ E, const float* __restrict__ Kp,
        const float* __restrict__ danger, const float* __restrict__ w_prev,
        const float* __restrict__ fitness, const float* __restrict__ crisis,
        const float* __restrict__ proto_conf,
        float* __restrict__ out_w, float* __restrict__ out_P)
{
    extern __shared__ char sm[];
    const int tid  = threadIdx.x;
    const int w    = tid >> 5, lane = tid & 31;
    const int bg   = blockIdx.x;
    const uint32_t smb = smem_u32(sm);

    float* Y     = (float*)(sm + OFF_Y);
    float* sDang = (float*)(sm + OFF_DANG);
    float* rowst = (float*)(sm + OFF_ROWST);
    float* sStat = (float*)(sm + OFF_STATS);

    // ---- load danger (4 batches)
    for (int i = tid; i < GB * 256; i += 256) {
        int b4 = i >> 8;
        sDang[i] = danger[(size_t)(bg * GB + b4) * 256 + (i & 255)];
    }
    __syncthreads();

    // ---- per-thread A-row mapping: thread t -> row t>>2, col quarter (t&3)*16
    const int arow = tid >> 2;
    const int q    = tid & 3;
    const int rr   = arow < ROWS ? arow : ROWS - 1;
    const int b4row = rr / 14;
    const int wr    = rr % 14;
    const int batchR = bg * GB + b4row;
    const float* srcRow = (wr < 6) ? (E  + ((size_t)batchR * 6 + wr) * 256)
                                   : (Kp + ((size_t)batchR * 8 + (wr - 6)) * 256);
    const float* dang = sDang + b4row * 256;

    float sd = 0.f, s0 = 0.f, s1 = 0.f, s2 = 0.f, s3 = 0.f, snrm = 0.f;

    // ---- accumulators: [eh][mt][nt][4]
    float acc[2][2][4][4];
    #pragma unroll
    for (int eh = 0; eh < 2; eh++)
        #pragma unroll
        for (int mt = 0; mt < 2; mt++)
            #pragma unroll
            for (int nt = 0; nt < 4; nt++)
                #pragma unroll
                for (int j = 0; j < 4; j++) acc[eh][mt][nt][j] = 0.f;

    const int mbase = (w & 1) * 32;
    const int nbase = (w >> 1) * 32;
    const int arw   = mbase + (lane & 15);
    const int nrw   = nbase + (lane & 7) + ((lane >> 4) << 3);

    // ---- main loop over k-chunks
    #pragma unroll
    for (int c = 0; c < 4; c++) {
        // A convert (+ stats on fp32 values)
        {
            const float4* s4 = (const float4*)(srcRow + c * 64 + q * 16);
            char* ah = sm + OFF_AH;
            char* al = sm + OFF_AL;
            #pragma unroll
            for (int j = 0; j < 4; j++) {
                float4 v = s4[j];
                int kc  = q * 16 + j * 4;
                int col = c * 64 + kc;
                sd   = fmaf(v.x, dang[col],   fmaf(v.y, dang[col+1],   fmaf(v.z, dang[col+2],   fmaf(v.w, dang[col+3],   sd))));
                s0   = fmaf(v.x, g_signorm[col],     fmaf(v.y, g_signorm[col+1],     fmaf(v.z, g_signorm[col+2],     fmaf(v.w, g_signorm[col+3],     s0))));
                s1   = fmaf(v.x, g_signorm[256+col], fmaf(v.y, g_signorm[256+col+1], fmaf(v.z, g_signorm[256+col+2], fmaf(v.w, g_signorm[256+col+3], s1))));
                s2   = fmaf(v.x, g_signorm[512+col], fmaf(v.y, g_signorm[512+col+1], fmaf(v.z, g_signorm[512+col+2], fmaf(v.w, g_signorm[512+col+3], s2))));
                s3   = fmaf(v.x, g_signorm[768+col], fmaf(v.y, g_signorm[768+col+1], fmaf(v.z, g_signorm[768+col+2], fmaf(v.w, g_signorm[768+col+3], s3))));
                snrm = fmaf(v.x, v.x, fmaf(v.y, v.y, fmaf(v.z, v.z, fmaf(v.w, v.w, snrm))));

                __nv_bfloat16 h0 = __float2bfloat16(v.x);
                __nv_bfloat16 h1 = __float2bfloat16(v.y);
                __nv_bfloat16 h2 = __float2bfloat16(v.z);
                __nv_bfloat16 h3 = __float2bfloat16(v.w);
                __nv_bfloat16 l0 = __float2bfloat16(v.x - __bfloat162float(h0));
                __nv_bfloat16 l1 = __float2bfloat16(v.y - __bfloat162float(h1));
                __nv_bfloat16 l2 = __float2bfloat16(v.z - __bfloat162float(h2));
                __nv_bfloat16 l3 = __float2bfloat16(v.w - __bfloat162float(h3));
                uint32_t off = SWZ128((uint32_t)(arow * 128 + kc * 2));
                __nv_bfloat162 hA; hA.x = h0; hA.y = h1;
                __nv_bfloat162 hB; hB.x = h2; hB.y = h3;
                __nv_bfloat162 lA; lA.x = l0; lA.y = l1;
                __nv_bfloat162 lB; lB.x = l2; lB.y = l3;
                *(__nv_bfloat162*)(ah + off)     = hA;
                *(__nv_bfloat162*)(ah + off + 4) = hB;
                *(__nv_bfloat162*)(al + off)     = lA;
                *(__nv_bfloat162*)(al + off + 4) = lB;
            }
        }
        __syncthreads();

        #pragma unroll
        for (int eh = 0; eh < 2; eh++) {
            // B load: 16KB hi + 16KB lo
            {
                const float4* gh = (const float4*)((const char*)g_Lh + c * 32768 + eh * 16384);
                const float4* gl = (const float4*)((const char*)g_Ll + c * 32768 + eh * 16384);
                float4* bh4 = (float4*)(sm + OFF_BH);
                float4* bl4 = (float4*)(sm + OFF_BL);
                #pragma unroll
                for (int i = 0; i < 4; i++) {
                    bh4[tid + i * 256] = gh[tid + i * 256];
                    bl4[tid + i * 256] = gl[tid + i * 256];
                }
            }
            __syncthreads();

            // mma over 4 k-steps
            {
                const uint32_t aH = smb + OFF_AH, aL = smb + OFF_AL;
                const uint32_t bH = smb + OFF_BH, bL = smb + OFF_BL;
                #pragma unroll
                for (int ks = 0; ks < 4; ks++) {
                    uint32_t ah[2][4], al[2][4], bh[2][4], bl[2][4];
                    const int akc = ks * 16 + (lane >> 4) * 8;
                    const int bkc = ks * 16 + ((lane >> 3) & 1) * 8;
                    #pragma unroll
                    for (int mt = 0; mt < 2; mt++) {
                        uint32_t off = SWZ128((uint32_t)((arw + mt * 16) * 128 + akc * 2));
                        LDSM4(ah[mt], aH + off);
                        LDSM4(al[mt], aL + off);
                    }
                    #pragma unroll
                    for (int g = 0; g < 2; g++) {
                        uint32_t off = SWZ128((uint32_t)((nrw + g * 16) * 128 + bkc * 2));
                        LDSM4(bh[g], bH + off);
                        LDSM4(bl[g], bL + off);
                    }
                    #pragma unroll
                    for (int mt = 0; mt < 2; mt++)
                        #pragma unroll
                        for (int nt = 0; nt < 4; nt++) {
                            uint32_t* Bh = &bh[nt >> 1][(nt & 1) * 2];
                            uint32_t* Bl = &bl[nt >> 1][(nt & 1) * 2];
                            MMA_BF16(acc[eh][mt][nt], ah[mt], Bh);
                            MMA_BF16(acc[eh][mt][nt], ah[mt], Bl);
                            MMA_BF16(acc[eh][mt][nt], al[mt], Bh);
                        }
                }
            }
            __syncthreads();
        }
    }

    // ---- reduce per-row stats across the 4 col-quarter threads (width 4)
    sd   += __shfl_xor_sync(~0u, sd,   1, 4);  sd   += __shfl_xor_sync(~0u, sd,   2, 4);
    s0   += __shfl_xor_sync(~0u, s0,   1, 4);  s0   += __shfl_xor_sync(~0u, s0,   2, 4);
    s1   += __shfl_xor_sync(~0u, s1,   1, 4);  s1   += __shfl_xor_sync(~0u, s1,   2, 4);
    s2   += __shfl_xor_sync(~0u, s2,   1, 4);  s2   += __shfl_xor_sync(~0u, s2,   2, 4);
    s3   += __shfl_xor_sync(~0u, s3,   1, 4);  s3   += __shfl_xor_sync(~0u, s3,   2, 4);
    snrm += __shfl_xor_sync(~0u, snrm, 1, 4);  snrm += __shfl_xor_sync(~0u, snrm, 2, 4);
    if (q == 0 && arow < ROWS) {
        float* rs = rowst + arow * 6;
        rs[0] = sd; rs[1] = s0; rs[2] = s1; rs[3] = s2; rs[4] = s3; rs[5] = snrm;
    }

    // ---- store Y tile to smem (guard rows >= 56)
    #pragma unroll
    for (int eh = 0; eh < 2; eh++)
        #pragma unroll
        for (int mt = 0; mt < 2; mt++) {
            const int row = mbase + mt * 16 + (lane >> 2);
            #pragma unroll
            for (int nt = 0; nt < 4; nt++) {
                const int col = eh * 128 + nbase + nt * 8 + (lane & 3) * 2;
                if (row < ROWS)
                    *(float2*)(Y + row * 256 + col)       = make_float2(acc[eh][mt][nt][0], acc[eh][mt][nt][1]);
                if (row + 8 < ROWS)
                    *(float2*)(Y + (row + 8) * 256 + col) = make_float2(acc[eh][mt][nt][2], acc[eh][mt][nt][3]);
            }
        }
    __syncthreads();

    // ---- phase 2a: 62 reductions per batch (48 cross + 6 E-norm + 8 K-norm)
    {
        const float4* Y4 = (const float4*)Y;
        for (int u = w; u < GB * 62; u += 8) {
            int bl_ = u / 62, t = u - bl_ * 62;
            int rA, rB;
            if (t < 48)      { rA = bl_ * 14 + (t >> 3); rB = bl_ * 14 + 6 + (t & 7); }
            else if (t < 54) { rA = bl_ * 14 + (t - 48);       rB = rA; }
            else             { rA = bl_ * 14 + 6 + (t - 54);   rB = rA; }
            float4 a0 = Y4[rA * 64 + lane * 2];
            float4 a1 = Y4[rA * 64 + lane * 2 + 1];
            float4 b0 = Y4[rB * 64 + lane * 2];
            float4 b1 = Y4[rB * 64 + lane * 2 + 1];
            float s = a0.x*b0.x + a0.y*b0.y + a0.z*b0.z + a0.w*b0.w
                    + a1.x*b1.x + a1.y*b1.y + a1.z*b1.z + a1.w*b1.w;
            #pragma unroll
            for (int o = 16; o; o >>= 1) s += __shfl_xor_sync(~0u, s, o);
            if (lane == 0) sStat[u] = s;
        }
    }
    __syncthreads();

    // ---- phase 2b: C build + Sinkhorn + replicator (warp b handles batch b)
    if (w < GB) {
        const int batch = bg * GB + w;
        const float* st = sStat + w * 62;
        const int n = lane & 7;
        const float nK = st[54 + n];

        const float* rsk = rowst + (w * 14 + 6 + n) * 6;
        float kn  = fmaxf(sqrtf(rsk[5]), 1e-12f);
        float pss = fmaxf(fmaxf(rsk[1], rsk[2]), fmaxf(rsk[3], rsk[4])) / kn;

        const float pc = proto_conf[(size_t)batch * 8 + n];

        const float INV_EPS = 1.0f / (0.05f + 1e-8f);
        const float LOG_U = logf(1.0f / 6.0f + 1e-8f);
        const float LOG_V = logf(0.125f     + 1e-8f);
        float lk[6], la[6], lb = 0.0f;
        #pragma unroll
        for (int m = 0; m < 6; m++) {
            const float* rse = rowst + (w * 14 + m) * 6;
            float en    = fmaxf(sqrtf(rse[5]), 1e-12f);
            float worst = fmaxf(fmaxf(rse[1], rse[2]), fmaxf(rse[3], rse[4])) / en;
            float tp    = fmaxf(worst - 0.1f, 0.0f);
            float msq   = st[48 + m] + nK - 2.0f * st[m * 8 + n];
            float dist  = sqrtf(fmaxf(msq, 1e-8f));
            float C     = dist - 0.5f * rse[0] + 2.0f * tp + 0.3f * pc;
            lk[m] = -C * INV_EPS;
            la[m] = 0.f;
        }

        for (int it = 0; it < 10; it++) {
            float t2[6];
            #pragma unroll
            for (int m = 0; m < 6; m++) {
                float t = lk[m] + lb;
                float r = t;
                r = fmaxf(r, __shfl_xor_sync(~0u, r, 1, 8));
                r = fmaxf(r, __shfl_xor_sync(~0u, r, 2, 8));
                r = fmaxf(r, __shfl_xor_sync(~0u, r, 4, 8));
                float s = expf(t - r);
                s += __shfl_xor_sync(~0u, s, 1, 8);
                s += __shfl_xor_sync(~0u, s, 2, 8);
                s += __shfl_xor_sync(~0u, s, 4, 8);
                la[m] = LOG_U - (r + logf(s));
                t2[m] = lk[m] + la[m];
            }
            float cm = t2[0];
            #pragma unroll
            for (int m = 1; m < 6; m++) cm = fmaxf(cm, t2[m]);
            float cs = 0.f;
            #pragma unroll
            for (int m = 0; m < 6; m++) cs += expf(t2[m] - cm);
            lb = LOG_V - (cm + logf(cs));
        }

        float pm = 0.0f;
        #pragma unroll
        for (int m = 0; m < 6; m++) {
            float p = expf(la[m] + lk[m] + lb);
            p = fminf(fmaxf(p, 0.0f), 1.0f);
            if (lane < 8) out_P[(size_t)batch * 48 + m * 8 + n] = p;
            pm += p;
        }

        float wp  = w_prev [(size_t)batch * 8 + n];
        float fit = fitness[(size_t)batch * 8 + n];
        float bl = wp * fit;
        bl += __shfl_xor_sync(~0u, bl, 1, 8);
        bl += __shfl_xor_sync(~0u, bl, 2, 8);
        bl += __shfl_xor_sync(~0u, bl, 4, 8);
        float eta = 0.05f + 0.1f * crisis[batch];
        float lt = logf(wp + 1e-8f) + eta * (fit - bl) - 0.5f * pss;
        float mx = lt;
        mx = fmaxf(mx, __shfl_xor_sync(~0u, mx, 1, 8));
        mx = fmaxf(mx, __shfl_xor_sync(~0u, mx, 2, 8));
        mx = fmaxf(mx, __shfl_xor_sync(~0u, mx, 4, 8));
        float ex = expf(lt - mx);
        float ss = ex;
        ss += __shfl_xor_sync(~0u, ss, 1, 8);
        ss += __shfl_xor_sync(~0u, ss, 2, 8);
        ss += __shfl_xor_sync(~0u, ss, 4, 8);
        float tilde = ex / ss;
        float wv = 0.7f * tilde + 0.3f * pm;
        float ws = wv;
        ws += __shfl_xor_sync(~0u, ws, 1, 8);
        ws += __shfl_xor_sync(~0u, ws, 2, 8);
        ws += __shfl_xor_sync(~0u, ws, 4, 8);
        wv = wv / (ws + 1e-8f);
        wv = fminf(fmaxf(wv, 1e-6f), 1.0f);
        if (lane < 8) out_w[(size_t)batch * 8 + n] = wv;
    }
}

// ---------------- launch ----------------
extern "C" void kernel_launch(void* const* d_in, const int* in_sizes, int n_in,
                              void* d_out, int out_size)
{
    const float* E          = (const float*)d_in[0];
    const float* K          = (const float*)d_in[1];
    const float* danger     = (const float*)d_in[2];
    const float* w_prev     = (const float*)d_in[3];
    const float* fitness    = (const float*)d_in[4];
    const float* crisis     = (const float*)d_in[5];
    const float* proto_conf = (const float*)d_in[6];
    const float* metric_L   = (const float*)d_in[7];
    const float* self_sigs  = (const float*)d_in[8];

    float* out   = (float*)d_out;
    float* out_w = out;                       // [B, 8]
    float* out_P = out + (size_t)NB * 8;      // [B, 6, 8]

    cudaFuncSetAttribute(k_fused, cudaFuncAttributeMaxDynamicSharedMemorySize,
                         SMEM_TOT);

    k_signorm<<<1, 128>>>(self_sigs);
    k_prepL<<<256, 256>>>(metric_L);
    k_fused<<<NB / GB, 256, SMEM_TOT>>>(E, K, danger, w_prev, fitness, crisis,
                                        proto_conf, out_w, out_P);
}